// round 1
// baseline (speedup 1.0000x reference)
#include <cuda_runtime.h>

// ---------------- constants ----------------
#define PI16 0.19634954084936207f   // pi/16

static __constant__ float c_ytab[64] = {
 16,11,10,16,24,40,51,61,
 12,12,14,19,26,58,60,55,
 14,13,16,24,40,57,69,56,
 14,17,22,29,51,87,80,62,
 18,22,37,56,68,109,103,77,
 24,35,55,64,81,104,113,92,
 49,64,78,87,103,121,120,101,
 72,92,95,98,112,100,103,99};

static __constant__ float c_ctab[64] = {
 17,18,24,47,99,99,99,99,
 18,21,26,66,99,99,99,99,
 24,26,56,99,99,99,99,99,
 47,66,99,99,99,99,99,99,
 99,99,99,99,99,99,99,99,
 99,99,99,99,99,99,99,99,
 99,99,99,99,99,99,99,99,
 99,99,99,99,99,99,99,99};

// H = W = 512 fixed by the problem (verified against in_sizes in kernel_launch).
#define IMG_H 512
#define IMG_W 512
#define TILES_X 32            // W/16
#define TILES_PER_IMG 1024    // 32*32
#define Y_BLOCKS_PER_IMG 4096 // (512/8)^2
#define C_BLOCKS_PER_IMG 1024 // (256/8)^2

__global__ __launch_bounds__(256)
void jpeg_fused_kernel(const float* __restrict__ x,
                       const float* __restrict__ fac,
                       float* __restrict__ out,
                       int B)
{
    __shared__ float cosT[8][8];      // cosT[x][u] = cos((2x+1)u pi/16)
    __shared__ float scl[8][8];       // 0.25 * alpha_u * alpha_v
    __shared__ float blk[6][8][9];    // 4 Y blocks, cb, cr (DCT inputs)
    __shared__ float tmpv[6][8][9];   // pass-1 intermediate
    __shared__ float cbs[16][17];
    __shared__ float crs[16][17];

    const int tid = threadIdx.x;

    // ---- one-time per-CTA table build (cheap: 64 cosf) ----
    if (tid < 64) {
        int a = tid >> 3, bI = tid & 7;
        cosT[a][bI] = cosf((float)((2*a + 1) * bI) * PI16);
        float au = (a  == 0) ? 0.70710678118654752f : 1.0f;
        float av = (bI == 0) ? 0.70710678118654752f : 1.0f;
        scl[a][bI] = 0.25f * au * av;
    }

    // ---- tile decode ----
    const int t   = blockIdx.x;
    const int b   = t >> 10;          // / TILES_PER_IMG
    const int rem = t & 1023;
    const int tr  = rem >> 5;         // tile row (0..31)
    const int tc  = rem & 31;         // tile col (0..31)

    // ---- pixel stage: RGB -> YCbCr ----
    const int py = tid >> 4;          // 0..15
    const int px = tid & 15;          // 0..15
    const size_t plane = (size_t)IMG_H * IMG_W;
    const float* p = x + (size_t)b * 3 * plane
                       + (size_t)(tr * 16 + py) * IMG_W + (tc * 16 + px);
    const float r  = p[0];
    const float g  = p[plane];
    const float bl = p[2 * plane];

    // img = x*255 ; ycc = img @ M (+128 on chroma cancels against DCT's -128)
    const float Y  = ( 0.299f    * r + 0.587f    * g + 0.114f    * bl) * 255.0f;
    const float Cb = (-0.168736f * r - 0.331264f * g + 0.5f      * bl) * 255.0f;
    const float Cr = ( 0.5f      * r - 0.418688f * g - 0.081312f * bl) * 255.0f;

    const int bq = ((py >> 3) << 1) | (px >> 3);   // which of 4 Y blocks
    blk[bq][py & 7][px & 7] = Y - 128.0f;
    cbs[py][px] = Cb;
    crs[py][px] = Cr;
    __syncthreads();

    // ---- 2x2 avg pool for chroma (the +128/-128 pair cancels) ----
    if (tid < 64) {
        int pr = tid >> 3, pc = tid & 7;
        int r2 = pr << 1, c2 = pc << 1;
        blk[4][pr][pc] = 0.25f * (cbs[r2][c2] + cbs[r2][c2+1] +
                                  cbs[r2+1][c2] + cbs[r2+1][c2+1]);
        blk[5][pr][pc] = 0.25f * (crs[r2][c2] + crs[r2][c2+1] +
                                  crs[r2+1][c2] + crs[r2+1][c2+1]);
    }
    __syncthreads();

    // ---- DCT pass 1: tmp[q][u][y] = sum_x cos[x][u] * blk[q][x][y] ----
    for (int i = tid; i < 384; i += 256) {
        const int q = i >> 6, j = i & 63, u = j >> 3, yc = j & 7;
        float s = 0.0f;
        #pragma unroll
        for (int xx = 0; xx < 8; xx++)
            s = fmaf(cosT[xx][u], blk[q][xx][yc], s);
        tmpv[q][u][yc] = s;
    }
    __syncthreads();

    // ---- DCT pass 2 + quantize + diff_round + store ----
    const float f = __ldg(&fac[b]);
    const size_t YTOT = (size_t)B * Y_BLOCKS_PER_IMG * 64;
    const size_t CTOT = (size_t)B * C_BLOCKS_PER_IMG * 64;

    for (int i = tid; i < 384; i += 256) {
        const int q = i >> 6, j = i & 63, u = j >> 3, v = j & 7;
        float s = 0.0f;
        #pragma unroll
        for (int yc = 0; yc < 8; yc++)
            s = fmaf(tmpv[q][u][yc], cosT[yc][v], s);
        const float d   = scl[u][v] * s;
        const float tab = (q < 4) ? c_ytab[j] : c_ctab[j];
        const float qt  = d / (tab * f);
        const float rr  = rintf(qt);           // round-half-even, matches jnp.round
        const float e   = qt - rr;
        const float res = rr + e * e * e;      // diff_round

        size_t addr;
        if (q < 4) {
            const int h8 = (tr << 1) + (q >> 1);
            const int w8 = (tc << 1) + (q & 1);
            addr = (size_t)b * (Y_BLOCKS_PER_IMG * 64)
                 + (size_t)(h8 * 64 + w8) * 64 + j;
        } else {
            const int n = tr * TILES_X + tc;
            addr = YTOT + ((q == 5) ? CTOT : 0)
                 + (size_t)b * (C_BLOCKS_PER_IMG * 64)
                 + (size_t)n * 64 + j;
        }
        out[addr] = res;
    }
}

extern "C" void kernel_launch(void* const* d_in, const int* in_sizes, int n_in,
                              void* d_out, int out_size)
{
    const float* x   = (const float*)d_in[0];   // [B,3,512,512]
    const float* fac = (const float*)d_in[1];   // [B]
    float* out = (float*)d_out;                 // y_q | cb_q | cr_q concatenated

    const int B = in_sizes[1];
    const int grid = B * TILES_PER_IMG;         // one CTA per 16x16 pixel tile
    jpeg_fused_kernel<<<grid, 256>>>(x, fac, out, B);
}

// round 2
// speedup vs baseline: 2.9955x; 2.9955x over previous
#include <cuda_runtime.h>

// ---------------- quant tables ----------------
static __constant__ float c_ytab[64] = {
 16,11,10,16,24,40,51,61,
 12,12,14,19,26,58,60,55,
 14,13,16,24,40,57,69,56,
 14,17,22,29,51,87,80,62,
 18,22,37,56,68,109,103,77,
 24,35,55,64,81,104,113,92,
 49,64,78,87,103,121,120,101,
 72,92,95,98,112,100,103,99};

static __constant__ float c_ctab[64] = {
 17,18,24,47,99,99,99,99,
 18,21,26,66,99,99,99,99,
 24,26,56,99,99,99,99,99,
 47,66,99,99,99,99,99,99,
 99,99,99,99,99,99,99,99,
 99,99,99,99,99,99,99,99,
 99,99,99,99,99,99,99,99,
 99,99,99,99,99,99,99,99};

// cos((2x+1)u * pi/16) as compile-time literals
#define Kc1 0.980785280403230449f
#define Kc2 0.923879532511286756f
#define Kc3 0.831469612302545237f
#define Kc4 0.707106781186547524f
#define Kc5 0.555570233019602225f
#define Kc6 0.382683432365089772f
#define Kc7 0.195090322016128268f

#define IMG_W 512
#define TILES_PER_IMG 256   // (512/32)^2
#define Y_BLOCKS_PER_IMG 4096
#define C_BLOCKS_PER_IMG 1024

__global__ __launch_bounds__(256)
void jpeg_fused_kernel(const float* __restrict__ x,
                       const float* __restrict__ fac,
                       float* __restrict__ out,
                       int B)
{
    constexpr float CT[8][8] = {
      {1.f,  Kc1,  Kc2,  Kc3,  Kc4,  Kc5,  Kc6,  Kc7},
      {1.f,  Kc3,  Kc6, -Kc7, -Kc4, -Kc1, -Kc2, -Kc5},
      {1.f,  Kc5, -Kc6, -Kc1, -Kc4,  Kc7,  Kc2,  Kc3},
      {1.f,  Kc7, -Kc2, -Kc5,  Kc4,  Kc3, -Kc6, -Kc1},
      {1.f, -Kc7, -Kc2,  Kc5,  Kc4, -Kc3, -Kc6,  Kc1},
      {1.f, -Kc5, -Kc6,  Kc1, -Kc4, -Kc7,  Kc2, -Kc3},
      {1.f, -Kc3,  Kc6,  Kc7, -Kc4,  Kc1, -Kc2,  Kc5},
      {1.f, -Kc1,  Kc2, -Kc3,  Kc4, -Kc5,  Kc6, -Kc7}};

    __shared__ float blkS[24 * 64];   // 16 Y + 4 Cb + 4 Cr blocks, rows of 8
    __shared__ float tmpS[24 * 72];   // transpose buffer, [8][9] per block
    __shared__ float rtab[128];       // 1/ytab | 1/ctab

    const int tid = threadIdx.x;
    if (tid < 128)
        rtab[tid] = 1.0f / ((tid < 64) ? c_ytab[tid] : c_ctab[tid - 64]);

    const int t   = blockIdx.x;
    const int b   = t >> 8;
    const int rem = t & 255;
    const int tr  = rem >> 4;   // 32px tile row (0..15)
    const int tc  = rem & 15;   // 32px tile col (0..15)

    // -------- stage 1: vectorized pixel load, RGB->YCbCr, chroma pool --------
    const int ty  = tid >> 3;   // 0..31  (pixel row in tile)
    const int tx4 = tid & 7;    // 0..7   (group of 4 cols)
    const size_t plane = (size_t)IMG_W * IMG_W;
    const float* p = x + (size_t)b * 3 * plane
                       + (size_t)(tr * 32 + ty) * IMG_W + (tc * 32 + tx4 * 4);
    const float4 R  = *(const float4*)p;
    const float4 G  = *(const float4*)(p + plane);
    const float4 Bl = *(const float4*)(p + 2 * plane);

    // Y-128 (the +128/-128 cancels for chroma)
    float4 Yv;
    Yv.x = fmaf(76.245f, R.x, fmaf(149.685f, G.x, fmaf(29.07f, Bl.x, -128.0f)));
    Yv.y = fmaf(76.245f, R.y, fmaf(149.685f, G.y, fmaf(29.07f, Bl.y, -128.0f)));
    Yv.z = fmaf(76.245f, R.z, fmaf(149.685f, G.z, fmaf(29.07f, Bl.z, -128.0f)));
    Yv.w = fmaf(76.245f, R.w, fmaf(149.685f, G.w, fmaf(29.07f, Bl.w, -128.0f)));

    const int ybi = ((ty >> 3) << 2) | (tx4 >> 1);
    *(float4*)&blkS[ybi * 64 + (ty & 7) * 8 + (tx4 & 1) * 4] = Yv;

    // chroma (scaled by 255, shift cancelled)
    float cb0 = (-0.168736f * R.x - 0.331264f * G.x + 0.5f * Bl.x) * 255.0f;
    float cb1 = (-0.168736f * R.y - 0.331264f * G.y + 0.5f * Bl.y) * 255.0f;
    float cb2 = (-0.168736f * R.z - 0.331264f * G.z + 0.5f * Bl.z) * 255.0f;
    float cb3 = (-0.168736f * R.w - 0.331264f * G.w + 0.5f * Bl.w) * 255.0f;
    float cr0 = ( 0.5f * R.x - 0.418688f * G.x - 0.081312f * Bl.x) * 255.0f;
    float cr1 = ( 0.5f * R.y - 0.418688f * G.y - 0.081312f * Bl.y) * 255.0f;
    float cr2 = ( 0.5f * R.z - 0.418688f * G.z - 0.081312f * Bl.z) * 255.0f;
    float cr3 = ( 0.5f * R.w - 0.418688f * G.w - 0.081312f * Bl.w) * 255.0f;

    float hb0 = cb0 + cb1, hb1 = cb2 + cb3;
    float hr0 = cr0 + cr1, hr1 = cr2 + cr3;
    const unsigned FULL = 0xffffffffu;
    float ob0 = __shfl_xor_sync(FULL, hb0, 8);
    float ob1 = __shfl_xor_sync(FULL, hb1, 8);
    float or0 = __shfl_xor_sync(FULL, hr0, 8);
    float or1 = __shfl_xor_sync(FULL, hr1, 8);

    if ((ty & 1) == 0) {
        const int pr  = ty >> 1;                       // pooled row 0..15
        const int cbi = 16 + ((pr >> 3) << 1) + (tx4 >> 2);
        const int idx = cbi * 64 + (pr & 7) * 8 + (tx4 & 3) * 2;
        blkS[idx]           = 0.25f * (hb0 + ob0);
        blkS[idx + 1]       = 0.25f * (hb1 + ob1);
        blkS[idx + 4 * 64]     = 0.25f * (hr0 + or0);
        blkS[idx + 4 * 64 + 1] = 0.25f * (hr1 + or1);
    }

    const float fv = __ldg(&fac[b]);
    const float rf = 1.0f / fv;

    __syncthreads();

    // -------- stage 2: register DCT, one lane per block row --------
    if (tid < 192) {
        const int q  = tid >> 3;   // block 0..23 (warp owns 4 whole blocks)
        const int xr = tid & 7;    // row within block

        const float* rp = &blkS[q * 64 + xr * 8];
        const float4 a4 = *(const float4*)rp;
        const float4 b4 = *(const float4*)(rp + 4);
        const float r0 = a4.x, r1 = a4.y, r2 = a4.z, r3 = a4.w;
        const float r4 = b4.x, r5 = b4.y, r6 = b4.z, r7 = b4.w;

        // pass A over y: t[v] = sum_y r[y]*CT[y][v]  (all-immediate FMAs)
        float tv[8];
        #pragma unroll
        for (int v = 0; v < 8; v++) {
            float s = r0 * CT[0][v];
            s = fmaf(r1, CT[1][v], s);
            s = fmaf(r2, CT[2][v], s);
            s = fmaf(r3, CT[3][v], s);
            s = fmaf(r4, CT[4][v], s);
            s = fmaf(r5, CT[5][v], s);
            s = fmaf(r6, CT[6][v], s);
            s = fmaf(r7, CT[7][v], s);
            tv[v] = s;
        }

        // in-warp transpose via padded smem
        float* tp = &tmpS[q * 72 + xr * 9];
        #pragma unroll
        for (int v = 0; v < 8; v++) tp[v] = tv[v];
        __syncwarp();

        const int v = xr;   // this lane now owns column v
        float s[8];
        #pragma unroll
        for (int j = 0; j < 8; j++) s[j] = tmpS[q * 72 + j * 9 + v];

        // pass B over x: o[u] = sum_x s[x]*CT[x][u]
        float o[8];
        #pragma unroll
        for (int u = 0; u < 8; u++) {
            float acc = s[0] * CT[0][u];
            acc = fmaf(s[1], CT[1][u], acc);
            acc = fmaf(s[2], CT[2][u], acc);
            acc = fmaf(s[3], CT[3][u], acc);
            acc = fmaf(s[4], CT[4][u], acc);
            acc = fmaf(s[5], CT[5][u], acc);
            acc = fmaf(s[6], CT[6][u], acc);
            acc = fmaf(s[7], CT[7][u], acc);
            o[u] = acc;
        }

        // quantize + diff_round + store
        const float* rt = &rtab[(q < 16) ? 0 : 64];
        const float av = (v == 0) ? 0.70710678118654752f : 1.0f;
        const float sv = 0.25f * av * rf;   // fold 1/factor into the scale

        size_t base;
        if (q < 16) {
            const int h8 = tr * 4 + (q >> 2);
            const int w8 = tc * 4 + (q & 3);
            base = (size_t)b * (Y_BLOCKS_PER_IMG * 64)
                 + (size_t)(h8 * 64 + w8) * 64;
        } else {
            const int cq  = (q - 16) & 3;
            const int ch8 = tr * 2 + (cq >> 1);
            const int cw8 = tc * 2 + (cq & 1);
            base = (size_t)B * (Y_BLOCKS_PER_IMG * 64)
                 + ((q >= 20) ? (size_t)B * (C_BLOCKS_PER_IMG * 64) : 0)
                 + (size_t)b * (C_BLOCKS_PER_IMG * 64)
                 + (size_t)(ch8 * 32 + cw8) * 64;
        }

        #pragma unroll
        for (int u = 0; u < 8; u++) {
            const float au = (u == 0) ? 0.70710678118654752f : 1.0f;
            const float d  = o[u] * (au * sv);
            const float qt = d * rt[u * 8 + v];
            const float rr = rintf(qt);
            const float e  = qt - rr;
            out[base + u * 8 + v] = rr + e * e * e;
        }
    }
}

extern "C" void kernel_launch(void* const* d_in, const int* in_sizes, int n_in,
                              void* d_out, int out_size)
{
    const float* x   = (const float*)d_in[0];   // [B,3,512,512]
    const float* fac = (const float*)d_in[1];   // [B]
    float* out = (float*)d_out;

    const int B = in_sizes[1];
    const int grid = B * TILES_PER_IMG;         // one CTA per 32x32 pixel tile
    jpeg_fused_kernel<<<grid, 256>>>(x, fac, out, B);
}